// round 1
// baseline (speedup 1.0000x reference)
#include <cuda_runtime.h>

// Problem constants
constexpr int Bv = 16;
constexpr int Hv = 4;
constexpr int Dv = 64;     // head dim
constexpr int Cv = 256;    // channels = Hv*Dv
constexpr int Nv = 1024;   // sequence length (32*32)

// ---------------- static device scratch (no allocations allowed) -----------
__device__ float g_Q[(size_t)Bv * Cv * Nv];                 // [b][h*64+d][n]
__device__ float g_K[(size_t)Bv * Cv * Nv];
__device__ float g_V[(size_t)Bv * Cv * Nv];
__device__ float g_L[(size_t)Bv * Hv * Nv * Nv];            // logits / probs

// ---------------------------------------------------------------------------
// Kernel 1: QKV projection. Per batch: Y = Wcat(768x256) @ x_b(256x1024) + b.
// 64x64 tile, BK=16, 256 threads, 4x4 per thread.
// ---------------------------------------------------------------------------
__global__ void proj_kernel(const float* __restrict__ x,
                            const float* __restrict__ Wq, const float* __restrict__ bq,
                            const float* __restrict__ Wk, const float* __restrict__ bk,
                            const float* __restrict__ Wv, const float* __restrict__ bv) {
    const int b  = blockIdx.z;
    const int o0 = blockIdx.y * 64;        // 0..704 (12 tiles over 768 rows)
    const int n0 = blockIdx.x * 64;
    const int tid = threadIdx.x;           // 256 threads
    const int tx = tid & 15, ty = tid >> 4;

    const int which = o0 >> 8;             // 0:Q 1:K 2:V (64 | 256)
    const float* W    = (which == 0) ? Wq : (which == 1) ? Wk : Wv;
    const float* bias = (which == 0) ? bq : (which == 1) ? bk : bv;
    float* dst        = (which == 0) ? g_Q : (which == 1) ? g_K : g_V;
    const int or0 = o0 & 255;

    __shared__ float As[16][65];           // As[kk][oo] (padded: transposed stores)
    __shared__ float Bs[16][64];           // Bs[kk][nn]

    const float* xb = x + (size_t)b * Cv * Nv;

    float acc[4][4] = {};
    for (int k0 = 0; k0 < Cv; k0 += 16) {
        {   // A tile: W[or0+oo][k0+kk], coalesced along kk
            int oo = tid >> 4, kk = tid & 15;
            #pragma unroll
            for (int r = 0; r < 4; r++)
                As[kk][oo + r * 16] = W[(size_t)(or0 + oo + r * 16) * Cv + k0 + kk];
        }
        {   // B tile: x[b][k0+kk][n0+nn], coalesced along nn
            int nn = tid & 63, kk4 = tid >> 6;
            #pragma unroll
            for (int r = 0; r < 4; r++)
                Bs[kk4 + r * 4][nn] = xb[(size_t)(k0 + kk4 + r * 4) * Nv + n0 + nn];
        }
        __syncthreads();
        #pragma unroll
        for (int kk = 0; kk < 16; kk++) {
            float a[4], bb[4];
            #pragma unroll
            for (int i = 0; i < 4; i++) a[i] = As[kk][ty * 4 + i];
            #pragma unroll
            for (int j = 0; j < 4; j++) bb[j] = Bs[kk][tx * 4 + j];
            #pragma unroll
            for (int i = 0; i < 4; i++)
                #pragma unroll
                for (int j = 0; j < 4; j++)
                    acc[i][j] += a[i] * bb[j];
        }
        __syncthreads();
    }
    #pragma unroll
    for (int i = 0; i < 4; i++) {
        int orow = or0 + ty * 4 + i;
        float bval = bias[orow];
        float* drow = dst + ((size_t)b * Cv + orow) * Nv + n0 + tx * 4;
        #pragma unroll
        for (int j = 0; j < 4; j++) drow[j] = acc[i][j] + bval;
    }
}

// ---------------------------------------------------------------------------
// Kernel 2: logits. L[i][j] = sum_d Q[d][i]K[d][j] + R[d][i]Q[d][j]
// Folded as one GEMM over dd=128 with A=[Q;R], B=[K;Q].
// 128x128 tile, BK=16, 256 threads, 8x8 per thread.
// ---------------------------------------------------------------------------
__global__ void logits_kernel(const float* __restrict__ relh,
                              const float* __restrict__ relw) {
    const int bh = blockIdx.z;             // b*4+h
    const int h  = bh & 3;
    const int i0 = blockIdx.y * 128;
    const int j0 = blockIdx.x * 128;
    const int tid = threadIdx.x;           // 256
    const int tx = tid & 15, ty = tid >> 4;

    const float* Qbh = g_Q + (size_t)bh * Dv * Nv;
    const float* Kbh = g_K + (size_t)bh * Dv * Nv;
    float* Lbh = g_L + (size_t)bh * Nv * Nv;

    __shared__ __align__(16) float As[16][128];
    __shared__ __align__(16) float Bs[16][128];

    float acc[8][8] = {};

    for (int k0 = 0; k0 < 2 * Dv; k0 += 16) {
        #pragma unroll
        for (int r = 0; r < 2; r++) {
            int t  = tid + r * 256;        // 512 float4 slots per operand
            int kk = t >> 5, iv = t & 31;
            int kg = k0 + kk;
            // A side (rows i): [Q ; R]
            float4 av;
            if (kg < 64) {
                av = *(const float4*)(Qbh + (size_t)kg * Nv + i0 + iv * 4);
            } else {
                int d  = kg - 64;
                int gi = i0 + iv * 4;
                float4 rh = *(const float4*)(relh + ((size_t)h * 64 + d) * 32 + (gi & 31));
                float  rw = relw[((size_t)h * 64 + d) * 32 + (gi >> 5)];
                av = make_float4(rh.x + rw, rh.y + rw, rh.z + rw, rh.w + rw);
            }
            *(float4*)(&As[kk][iv * 4]) = av;
            // B side (cols j): [K ; Q]
            const float* Bsrc = (kg < 64) ? (Kbh + (size_t)kg * Nv)
                                          : (Qbh + (size_t)(kg - 64) * Nv);
            *(float4*)(&Bs[kk][iv * 4]) = *(const float4*)(Bsrc + j0 + iv * 4);
        }
        __syncthreads();
        #pragma unroll
        for (int kk = 0; kk < 16; kk++) {
            float a[8], bb[8];
            *(float4*)(a)      = *(const float4*)(&As[kk][ty * 8]);
            *(float4*)(a + 4)  = *(const float4*)(&As[kk][ty * 8 + 4]);
            *(float4*)(bb)     = *(const float4*)(&Bs[kk][tx * 8]);
            *(float4*)(bb + 4) = *(const float4*)(&Bs[kk][tx * 8 + 4]);
            #pragma unroll
            for (int i = 0; i < 8; i++)
                #pragma unroll
                for (int j = 0; j < 8; j++)
                    acc[i][j] += a[i] * bb[j];
        }
        __syncthreads();
    }
    #pragma unroll
    for (int i = 0; i < 8; i++) {
        float* row = Lbh + (size_t)(i0 + ty * 8 + i) * Nv + j0 + tx * 8;
        *(float4*)(row)     = make_float4(acc[i][0], acc[i][1], acc[i][2], acc[i][3]);
        *(float4*)(row + 4) = make_float4(acc[i][4], acc[i][5], acc[i][6], acc[i][7]);
    }
}

// ---------------------------------------------------------------------------
// Kernel 3: row softmax over j (1024 elems/row), 256 threads/row, float4 I/O.
// ---------------------------------------------------------------------------
__global__ void softmax_kernel() {
    const size_t row = blockIdx.x;         // 65536 rows
    float4* p = (float4*)(g_L + row * Nv);
    const int tid = threadIdx.x;           // 256

    float4 v = p[tid];
    float m = fmaxf(fmaxf(v.x, v.y), fmaxf(v.z, v.w));
    #pragma unroll
    for (int o = 16; o; o >>= 1) m = fmaxf(m, __shfl_xor_sync(0xffffffffu, m, o));

    __shared__ float redm[8];
    __shared__ float reds[8];
    if ((tid & 31) == 0) redm[tid >> 5] = m;
    __syncthreads();
    m = redm[0];
    #pragma unroll
    for (int i = 1; i < 8; i++) m = fmaxf(m, redm[i]);

    v.x = __expf(v.x - m); v.y = __expf(v.y - m);
    v.z = __expf(v.z - m); v.w = __expf(v.w - m);
    float s = v.x + v.y + v.z + v.w;
    #pragma unroll
    for (int o = 16; o; o >>= 1) s += __shfl_xor_sync(0xffffffffu, s, o);
    if ((tid & 31) == 0) reds[tid >> 5] = s;
    __syncthreads();
    s = reds[0];
    #pragma unroll
    for (int i = 1; i < 8; i++) s += reds[i];

    float inv = 1.0f / s;
    v.x *= inv; v.y *= inv; v.z *= inv; v.w *= inv;
    p[tid] = v;
}

// ---------------------------------------------------------------------------
// Kernel 4: out[d][m] = sum_n V[d][n] * P[m][n]  (both contiguous along n).
// 64x64 tile, BK=16, 256 threads, 4x4 per thread. d spans exactly 64.
// ---------------------------------------------------------------------------
__global__ void pv_kernel(float* __restrict__ out) {
    const int bh = blockIdx.z;
    const int m0 = blockIdx.x * 64;
    const int tid = threadIdx.x;           // 256
    const int tx = tid & 15, ty = tid >> 4;

    const float* Vbh = g_V + (size_t)bh * Dv * Nv;
    const float* Pbh = g_L + (size_t)bh * Nv * Nv;

    __shared__ float Vs[16][65];           // Vs[kk][dd]
    __shared__ float Ps[16][65];           // Ps[kk][mm]

    float acc[4][4] = {};
    const int rr = tid >> 2;               // 0..63 : dd / mm index
    const int kq = tid & 3;                // float4 slot along n

    for (int k0 = 0; k0 < Nv; k0 += 16) {
        float4 a = *(const float4*)(Vbh + (size_t)rr * Nv + k0 + kq * 4);
        Vs[kq * 4 + 0][rr] = a.x; Vs[kq * 4 + 1][rr] = a.y;
        Vs[kq * 4 + 2][rr] = a.z; Vs[kq * 4 + 3][rr] = a.w;
        float4 q = *(const float4*)(Pbh + (size_t)(m0 + rr) * Nv + k0 + kq * 4);
        Ps[kq * 4 + 0][rr] = q.x; Ps[kq * 4 + 1][rr] = q.y;
        Ps[kq * 4 + 2][rr] = q.z; Ps[kq * 4 + 3][rr] = q.w;
        __syncthreads();
        #pragma unroll
        for (int kk = 0; kk < 16; kk++) {
            float a2[4], b2[4];
            #pragma unroll
            for (int i = 0; i < 4; i++) a2[i] = Vs[kk][ty * 4 + i];
            #pragma unroll
            for (int j = 0; j < 4; j++) b2[j] = Ps[kk][tx * 4 + j];
            #pragma unroll
            for (int i = 0; i < 4; i++)
                #pragma unroll
                for (int j = 0; j < 4; j++)
                    acc[i][j] += a2[i] * b2[j];
        }
        __syncthreads();
    }
    #pragma unroll
    for (int i = 0; i < 4; i++) {
        int d = ty * 4 + i;
        float* row = out + ((size_t)bh * Dv + d) * Nv + m0 + tx * 4;
        #pragma unroll
        for (int j = 0; j < 4; j++) row[j] = acc[i][j];
    }
}

// ---------------------------------------------------------------------------
extern "C" void kernel_launch(void* const* d_in, const int* in_sizes, int n_in,
                              void* d_out, int out_size) {
    const float* x    = (const float*)d_in[0];
    const float* Wq   = (const float*)d_in[1];
    const float* bq   = (const float*)d_in[2];
    const float* Wk   = (const float*)d_in[3];
    const float* bk   = (const float*)d_in[4];
    const float* Wv   = (const float*)d_in[5];
    const float* bv   = (const float*)d_in[6];
    const float* relh = (const float*)d_in[7];
    const float* relw = (const float*)d_in[8];
    float* out = (float*)d_out;

    proj_kernel<<<dim3(Nv / 64, 768 / 64, Bv), 256>>>(x, Wq, bq, Wk, bk, Wv, bv);
    logits_kernel<<<dim3(Nv / 128, Nv / 128, Bv * Hv), 256>>>(relh, relw);
    softmax_kernel<<<Bv * Hv * Nv, 256>>>();
    pv_kernel<<<dim3(Nv / 64, 1, Bv * Hv), 256>>>(out);
}

// round 3
// speedup vs baseline: 1.4777x; 1.4777x over previous
#include <cuda_runtime.h>
#include <stdint.h>

// Problem constants
constexpr int Bv = 16;
constexpr int Hv = 4;
constexpr int Dv = 64;     // head dim
constexpr int Cv = 256;    // channels = Hv*Dv
constexpr int Nv = 1024;   // sequence length (32*32)

// ---------------- static device scratch (no allocations allowed) -----------
__device__ float g_Q[(size_t)Bv * Cv * Nv];                 // [bh][d][n]
__device__ float g_K[(size_t)Bv * Cv * Nv];
__device__ float g_V[(size_t)Bv * Cv * Nv];
__device__ float g_L[(size_t)Bv * Hv * Nv * Nv];            // logits / probs

// ---------------- small helpers --------------------------------------------
__device__ __forceinline__ float tf32_rna(float x) {
    uint32_t u;
    asm("cvt.rna.tf32.f32 %0, %1;" : "=r"(u) : "f"(x));
    return __uint_as_float(u);
}
__device__ __forceinline__ void tf32_split(float x, float& hi, float& lo) {
    hi = tf32_rna(x);
    lo = tf32_rna(x - hi);
}
// D += A(16x8,row) * B(8x8,col)   tf32
__device__ __forceinline__ void mma8(float acc[4],
                                     float a0, float a1, float a2, float a3,
                                     float b0, float b1) {
    asm volatile(
        "mma.sync.aligned.m16n8k8.row.col.f32.tf32.tf32.f32 "
        "{%0,%1,%2,%3},{%4,%5,%6,%7},{%8,%9},{%0,%1,%2,%3};\n"
        : "+f"(acc[0]), "+f"(acc[1]), "+f"(acc[2]), "+f"(acc[3])
        : "r"(__float_as_uint(a0)), "r"(__float_as_uint(a1)),
          "r"(__float_as_uint(a2)), "r"(__float_as_uint(a3)),
          "r"(__float_as_uint(b0)), "r"(__float_as_uint(b1)));
}

// ---------------------------------------------------------------------------
// Kernel 1: QKV projection (fp32 SIMT, exact). Y = Wcat(768x256) @ x_b + bias.
// ---------------------------------------------------------------------------
__global__ void proj_kernel(const float* __restrict__ x,
                            const float* __restrict__ Wq, const float* __restrict__ bq,
                            const float* __restrict__ Wk, const float* __restrict__ bk,
                            const float* __restrict__ Wv, const float* __restrict__ bv) {
    const int b  = blockIdx.z;
    const int o0 = blockIdx.y * 64;
    const int n0 = blockIdx.x * 64;
    const int tid = threadIdx.x;
    const int tx = tid & 15, ty = tid >> 4;

    const int which = o0 >> 8;
    const float* W    = (which == 0) ? Wq : (which == 1) ? Wk : Wv;
    const float* bias = (which == 0) ? bq : (which == 1) ? bk : bv;
    float* dst        = (which == 0) ? g_Q : (which == 1) ? g_K : g_V;
    const int or0 = o0 & 255;

    __shared__ float As[16][65];
    __shared__ float Bs[16][64];

    const float* xb = x + (size_t)b * Cv * Nv;

    float acc[4][4] = {};
    for (int k0 = 0; k0 < Cv; k0 += 16) {
        {
            int oo = tid >> 4, kk = tid & 15;
            #pragma unroll
            for (int r = 0; r < 4; r++)
                As[kk][oo + r * 16] = W[(size_t)(or0 + oo + r * 16) * Cv + k0 + kk];
        }
        {
            int nn = tid & 63, kk4 = tid >> 6;
            #pragma unroll
            for (int r = 0; r < 4; r++)
                Bs[kk4 + r * 4][nn] = xb[(size_t)(k0 + kk4 + r * 4) * Nv + n0 + nn];
        }
        __syncthreads();
        #pragma unroll
        for (int kk = 0; kk < 16; kk++) {
            float a[4], bb[4];
            #pragma unroll
            for (int i = 0; i < 4; i++) a[i] = As[kk][ty * 4 + i];
            #pragma unroll
            for (int j = 0; j < 4; j++) bb[j] = Bs[kk][tx * 4 + j];
            #pragma unroll
            for (int i = 0; i < 4; i++)
                #pragma unroll
                for (int j = 0; j < 4; j++)
                    acc[i][j] += a[i] * bb[j];
        }
        __syncthreads();
    }
    #pragma unroll
    for (int i = 0; i < 4; i++) {
        int orow = or0 + ty * 4 + i;
        float bval = bias[orow];
        float* drow = dst + ((size_t)b * Cv + orow) * Nv + n0 + tx * 4;
        #pragma unroll
        for (int j = 0; j < 4; j++) drow[j] = acc[i][j] + bval;
    }
}

// ---------------------------------------------------------------------------
// Kernel 2: logits via tensor cores (3xTF32 split => fp32-accurate).
// S[i][j] = sum_{dd=0..127} A[dd][i] * B[dd][j], A=[Q;R], B=[K;Q].
// CTA: 128x128 tile, 8 warps (warp tile 32x64), k-tile 16.
// ---------------------------------------------------------------------------
constexpr int SA = 136;   // smem row stride (floats): bank = (8k+i)&31 -> conflict-free
__global__ void __launch_bounds__(256, 2)
logits_mma_kernel(const float* __restrict__ relh, const float* __restrict__ relw) {
    const int bh = blockIdx.z;
    const int h  = bh & 3;
    const int i0 = blockIdx.y * 128;
    const int j0 = blockIdx.x * 128;
    const int tid = threadIdx.x;
    const int warp = tid >> 5, lane = tid & 31;
    const int g = lane >> 2, tig = lane & 3;
    const int wi = (warp >> 1) * 32;     // warp i-offset (4 rows of warps)
    const int wj = (warp & 1) * 64;      // warp j-offset (2 cols of warps)

    const float* Qbh = g_Q + (size_t)bh * Dv * Nv;
    const float* Kbh = g_K + (size_t)bh * Dv * Nv;
    float* Lbh = g_L + (size_t)bh * Nv * Nv;

    __shared__ float AsHi[16 * SA], AsLo[16 * SA];
    __shared__ float BsHi[16 * SA], BsLo[16 * SA];

    float acc[2][8][4] = {};

    for (int k0 = 0; k0 < 2 * Dv; k0 += 16) {
        // ---- stage: 16 x 128 fp32 tiles -> tf32 hi/lo in smem ----
        #pragma unroll
        for (int r = 0; r < 2; r++) {
            int t4 = tid + r * 256;            // 512 float4 slots
            int kk = t4 >> 5, iv = t4 & 31;
            int kg = k0 + kk;
            float4 av, bv4;
            if (kg < 64) {
                av  = *(const float4*)(Qbh + (size_t)kg * Nv + i0 + iv * 4);
                bv4 = *(const float4*)(Kbh + (size_t)kg * Nv + j0 + iv * 4);
            } else {
                int d  = kg - 64;
                int gi = i0 + iv * 4;
                float4 rh = *(const float4*)(relh + ((size_t)h * 64 + d) * 32 + (gi & 31));
                float  rw = relw[((size_t)h * 64 + d) * 32 + (gi >> 5)];
                av = make_float4(rh.x + rw, rh.y + rw, rh.z + rw, rh.w + rw);
                bv4 = *(const float4*)(Qbh + (size_t)d * Nv + j0 + iv * 4);
            }
            float4 ah, al, bhh, bl;
            tf32_split(av.x, ah.x, al.x); tf32_split(av.y, ah.y, al.y);
            tf32_split(av.z, ah.z, al.z); tf32_split(av.w, ah.w, al.w);
            tf32_split(bv4.x, bhh.x, bl.x); tf32_split(bv4.y, bhh.y, bl.y);
            tf32_split(bv4.z, bhh.z, bl.z); tf32_split(bv4.w, bhh.w, bl.w);
            *(float4*)(&AsHi[kk * SA + iv * 4]) = ah;
            *(float4*)(&AsLo[kk * SA + iv * 4]) = al;
            *(float4*)(&BsHi[kk * SA + iv * 4]) = bhh;
            *(float4*)(&BsLo[kk * SA + iv * 4]) = bl;
        }
        __syncthreads();

        // ---- 3 passes: hi*hi, hi*lo, lo*hi ----
        #pragma unroll
        for (int pass = 0; pass < 3; pass++) {
            const float* Ap = (pass < 2) ? AsHi : AsLo;
            const float* Bp = (pass == 1) ? BsLo : BsHi;
            #pragma unroll
            for (int ks = 0; ks < 2; ks++) {
                int kb = ks * 8;
                float a0[2], a1[2], a2[2], a3[2];
                #pragma unroll
                for (int ma = 0; ma < 2; ma++) {
                    int ib = wi + ma * 16 + g;
                    a0[ma] = Ap[(kb + tig) * SA + ib];
                    a1[ma] = Ap[(kb + tig) * SA + ib + 8];
                    a2[ma] = Ap[(kb + tig + 4) * SA + ib];
                    a3[ma] = Ap[(kb + tig + 4) * SA + ib + 8];
                }
                #pragma unroll
                for (int na = 0; na < 8; na++) {
                    int jb = wj + na * 8 + g;
                    float b0 = Bp[(kb + tig) * SA + jb];
                    float b1 = Bp[(kb + tig + 4) * SA + jb];
                    #pragma unroll
                    for (int ma = 0; ma < 2; ma++)
                        mma8(acc[ma][na], a0[ma], a1[ma], a2[ma], a3[ma], b0, b1);
                }
            }
        }
        __syncthreads();
    }

    // ---- epilogue ----
    #pragma unroll
    for (int ma = 0; ma < 2; ma++) {
        int ig = i0 + wi + ma * 16 + g;
        #pragma unroll
        for (int na = 0; na < 8; na++) {
            int jg = j0 + wj + na * 8 + 2 * tig;
            *(float2*)(Lbh + (size_t)ig * Nv + jg)       = make_float2(acc[ma][na][0], acc[ma][na][1]);
            *(float2*)(Lbh + (size_t)(ig + 8) * Nv + jg) = make_float2(acc[ma][na][2], acc[ma][na][3]);
        }
    }
}

// ---------------------------------------------------------------------------
// Kernel 3: row softmax over j (1024 elems/row).
// ---------------------------------------------------------------------------
__global__ void softmax_kernel() {
    const size_t row = blockIdx.x;
    float4* p = (float4*)(g_L + row * Nv);
    const int tid = threadIdx.x;

    float4 v = p[tid];
    float m = fmaxf(fmaxf(v.x, v.y), fmaxf(v.z, v.w));
    #pragma unroll
    for (int o = 16; o; o >>= 1) m = fmaxf(m, __shfl_xor_sync(0xffffffffu, m, o));

    __shared__ float redm[8];
    __shared__ float reds[8];
    if ((tid & 31) == 0) redm[tid >> 5] = m;
    __syncthreads();
    m = redm[0];
    #pragma unroll
    for (int i = 1; i < 8; i++) m = fmaxf(m, redm[i]);

    v.x = __expf(v.x - m); v.y = __expf(v.y - m);
    v.z = __expf(v.z - m); v.w = __expf(v.w - m);
    float s = v.x + v.y + v.z + v.w;
    #pragma unroll
    for (int o = 16; o; o >>= 1) s += __shfl_xor_sync(0xffffffffu, s, o);
    if ((tid & 31) == 0) reds[tid >> 5] = s;
    __syncthreads();
    s = reds[0];
    #pragma unroll
    for (int i = 1; i < 8; i++) s += reds[i];

    float inv = 1.0f / s;
    v.x *= inv; v.y *= inv; v.z *= inv; v.w *= inv;
    p[tid] = v;
}

// ---------------------------------------------------------------------------
// Kernel 4: PV via tensor cores (single-pass tf32, error ~2e-4).
// out[d][m] = sum_n V[d][n] * P[m][n].  A=V (row-major d x n), B=P^T (col-major).
// CTA: 64(d) x 256(m) tile, 8 warps (warp tile 32x64), k(n)-tile 16.
// ---------------------------------------------------------------------------
constexpr int SP = 20;    // smem row stride (floats)
__global__ void __launch_bounds__(256, 2)
pv_mma_kernel(float* __restrict__ out) {
    const int bh = blockIdx.z;
    const int m0 = blockIdx.x * 256;
    const int tid = threadIdx.x;
    const int warp = tid >> 5, lane = tid & 31;
    const int g = lane >> 2, tig = lane & 3;
    const int wd = (warp >> 2) * 32;     // warp d-offset (2)
    const int wm = (warp & 3) * 64;      // warp m-offset (4)

    const float* Vbh = g_V + (size_t)bh * Dv * Nv;
    const float* Pbh = g_L + (size_t)bh * Nv * Nv;

    __shared__ float Vs[64 * SP];
    __shared__ float Ps[256 * SP];

    float acc[2][8][4] = {};

    for (int n0 = 0; n0 < Nv; n0 += 16) {
        // stage V tile 64x16 (1 float4/thread), tf32-rounded
        {
            int t4 = tid;                    // 256 slots = 64 rows x 4 float4
            int d = t4 >> 2, c4 = t4 & 3;
            float4 v = *(const float4*)(Vbh + (size_t)d * Nv + n0 + c4 * 4);
            v.x = tf32_rna(v.x); v.y = tf32_rna(v.y);
            v.z = tf32_rna(v.z); v.w = tf32_rna(v.w);
            *(float4*)(&Vs[d * SP + c4 * 4]) = v;
        }
        // stage P tile 256x16 (4 float4/thread), tf32-rounded
        #pragma unroll
        for (int r = 0; r < 4; r++) {
            int t4 = tid + r * 256;          // 1024 slots = 256 rows x 4 float4
            int mrow = t4 >> 2, c4 = t4 & 3;
            float4 v = *(const float4*)(Pbh + (size_t)(m0 + mrow) * Nv + n0 + c4 * 4);
            v.x = tf32_rna(v.x); v.y = tf32_rna(v.y);
            v.z = tf32_rna(v.z); v.w = tf32_rna(v.w);
            *(float4*)(&Ps[mrow * SP + c4 * 4]) = v;
        }
        __syncthreads();

        #pragma unroll
        for (int ks = 0; ks < 2; ks++) {
            int kb = ks * 8;
            float a0[2], a1[2], a2[2], a3[2];
            #pragma unroll
            for (int ma = 0; ma < 2; ma++) {
                int db = wd + ma * 16 + g;
                a0[ma] = Vs[db * SP + kb + tig];
                a1[ma] = Vs[(db + 8) * SP + kb + tig];
                a2[ma] = Vs[db * SP + kb + tig + 4];
                a3[ma] = Vs[(db + 8) * SP + kb + tig + 4];
            }
            #pragma unroll
            for (int na = 0; na < 8; na++) {
                int mb = wm + na * 8 + g;
                float b0 = Ps[mb * SP + kb + tig];
                float b1 = Ps[mb * SP + kb + tig + 4];
                #pragma unroll
                for (int ma = 0; ma < 2; ma++)
                    mma8(acc[ma][na], a0[ma], a1[ma], a2[ma], a3[ma], b0, b1);
            }
        }
        __syncthreads();
    }

    // epilogue: out[bh*64 + d][m]
    #pragma unroll
    for (int ma = 0; ma < 2; ma++) {
        int dg = wd + ma * 16 + g;
        #pragma unroll
        for (int na = 0; na < 8; na++) {
            int mg = m0 + wm + na * 8 + 2 * tig;
            float* base0 = out + ((size_t)bh * Dv + dg) * Nv + mg;
            float* base1 = out + ((size_t)bh * Dv + dg + 8) * Nv + mg;
            *(float2*)base0 = make_float2(acc[ma][na][0], acc[ma][na][1]);
            *(float2*)base1 = make_float2(acc[ma][na][2], acc[ma][na][3]);
        }
    }
}

// ---------------------------------------------------------------------------
extern "C" void kernel_launch(void* const* d_in, const int* in_sizes, int n_in,
                              void* d_out, int out_size) {
    const float* x    = (const float*)d_in[0];
    const float* Wq   = (const float*)d_in[1];
    const float* bq   = (const float*)d_in[2];
    const float* Wk   = (const float*)d_in[3];
    const float* bk   = (const float*)d_in[4];
    const float* Wv   = (const float*)d_in[5];
    const float* bv   = (const float*)d_in[6];
    const float* relh = (const float*)d_in[7];
    const float* relw = (const float*)d_in[8];
    float* out = (float*)d_out;

    proj_kernel<<<dim3(Nv / 64, 768 / 64, Bv), 256>>>(x, Wq, bq, Wk, bk, Wv, bv);
    logits_mma_kernel<<<dim3(Nv / 128, Nv / 128, Bv * Hv), 256>>>(relh, relw);
    softmax_kernel<<<Bv * Hv * Nv, 256>>>();
    pv_mma_kernel<<<dim3(Nv / 256, 1, Bv * Hv), 256>>>(out);
}